// round 1
// baseline (speedup 1.0000x reference)
#include <cuda_runtime.h>

#define N_NODES 50000
#define N_EDGES 600000
#define F 128           // F_IN == F_OUT == 128
#define F4 (F / 4)      // 32 float4 per row

// Scratch (static device globals — no allocation)
__device__ float g_agg[(size_t)N_NODES * F];   // 25.6 MB
__device__ int   g_deg[N_NODES];

// ---------------------------------------------------------------------------
// Kernel 1: zero the scratch accumulators
// ---------------------------------------------------------------------------
__global__ void zero_kernel() {
    int idx = blockIdx.x * blockDim.x + threadIdx.x;
    const int total4 = N_NODES * F / 4;  // 1,600,000
    if (idx < total4) {
        ((float4*)g_agg)[idx] = make_float4(0.f, 0.f, 0.f, 0.f);
    }
    if (idx < N_NODES) {
        g_deg[idx] = 0;
    }
}

// ---------------------------------------------------------------------------
// Kernel 2: edge scatter-add. One warp per edge: 32 lanes x float4 = 512B row.
// Uses vector red.global.add.v4.f32 (sm_90+) -> 4x fewer atomic ops.
// ---------------------------------------------------------------------------
__global__ void edge_kernel(const float4* __restrict__ x4,
                            const int* __restrict__ src,
                            const int* __restrict__ dst) {
    int gw   = (blockIdx.x * blockDim.x + threadIdx.x) >> 5;
    int lane = threadIdx.x & 31;
    if (gw >= N_EDGES) return;

    int s = __ldg(&src[gw]);
    int d = __ldg(&dst[gw]);

    float4 v = x4[(size_t)s * F4 + lane];

    float* p = &g_agg[((size_t)d * F4 + lane) * 4];
    asm volatile("red.global.add.v4.f32 [%0], {%1,%2,%3,%4};"
                 :: "l"(p), "f"(v.x), "f"(v.y), "f"(v.z), "f"(v.w)
                 : "memory");

    if (lane == 0) atomicAdd(&g_deg[d], 1);
}

// ---------------------------------------------------------------------------
// Kernel 3: fused GEMM  out = relu(x @ Ws + (agg/deg) @ Wn + b)
// Persistent CTAs. Both weights cached fully in SMEM (128 KB).
// Tile: M=64 rows, N=128 cols, K=128 (x2 inputs). 256 threads, 8x4 micro-tile.
// ---------------------------------------------------------------------------
#define TILE_M 64
// SMEM layout (floats): Ws[16384] Wn[16384] A[8192] H[8192] Inv[64]
#define SM_WS   0
#define SM_WN   16384
#define SM_A    32768
#define SM_H    40960
#define SM_INV  49152
#define SMEM_FLOATS 49216
#define SMEM_BYTES (SMEM_FLOATS * 4)

__global__ void __launch_bounds__(256, 1)
gemm_kernel(const float* __restrict__ x,
            const float* __restrict__ Ws,
            const float* __restrict__ Wn,
            const float* __restrict__ bias,
            float* __restrict__ out) {
    extern __shared__ float sm[];
    float* sWs  = sm + SM_WS;
    float* sWn  = sm + SM_WN;
    float* sA   = sm + SM_A;
    float* sH   = sm + SM_H;
    float* sInv = sm + SM_INV;

    const int tid = threadIdx.x;
    const int tx  = tid & 31;   // column group: cols [4*tx, 4*tx+4)
    const int ty  = tid >> 5;   // row group:    rows [8*ty, 8*ty+8)

    // Load both weight matrices to SMEM once per CTA (coalesced float4).
    for (int i = tid; i < 16384 / 4; i += 256) {
        ((float4*)sWs)[i] = ((const float4*)Ws)[i];
        ((float4*)sWn)[i] = ((const float4*)Wn)[i];
    }
    const float4 bv = ((const float4*)bias)[tx];

    const int numTiles = (N_NODES + TILE_M - 1) / TILE_M;  // 782

    for (int tile = blockIdx.x; tile < numTiles; tile += gridDim.x) {
        const int row0 = tile * TILE_M;

        __syncthreads();   // previous tile's compute done before overwriting smem

        // Load A tile (x rows) + per-row 1/max(deg,1)
        #pragma unroll
        for (int j = 0; j < 8; ++j) {
            int i = j * 256 + tid;        // float4 index within 64x32 tile
            int r = i >> 5, c = i & 31;
            int node = row0 + r;
            ((float4*)sA)[i] = (node < N_NODES)
                ? ((const float4*)x)[(size_t)node * F4 + c]
                : make_float4(0.f, 0.f, 0.f, 0.f);
        }
        if (tid < TILE_M) {
            int node = row0 + tid;
            int d = (node < N_NODES) ? g_deg[node] : 1;
            sInv[tid] = 1.0f / (float)max(d, 1);
        }
        __syncthreads();

        // Load H tile = agg * (1/deg)
        #pragma unroll
        for (int j = 0; j < 8; ++j) {
            int i = j * 256 + tid;
            int r = i >> 5, c = i & 31;
            int node = row0 + r;
            float4 v = (node < N_NODES)
                ? ((const float4*)g_agg)[(size_t)node * F4 + c]
                : make_float4(0.f, 0.f, 0.f, 0.f);
            float iv = sInv[r];
            v.x *= iv; v.y *= iv; v.z *= iv; v.w *= iv;
            ((float4*)sH)[i] = v;
        }
        __syncthreads();

        float acc[8][4];
        #pragma unroll
        for (int r = 0; r < 8; ++r)
            #pragma unroll
            for (int c = 0; c < 4; ++c) acc[r][c] = 0.f;

        // ---- acc += A @ Ws ----
        #pragma unroll 2
        for (int k = 0; k < F; k += 4) {
            float4 b0 = *(const float4*)&sWs[(k + 0) * F + tx * 4];
            float4 b1 = *(const float4*)&sWs[(k + 1) * F + tx * 4];
            float4 b2 = *(const float4*)&sWs[(k + 2) * F + tx * 4];
            float4 b3 = *(const float4*)&sWs[(k + 3) * F + tx * 4];
            #pragma unroll
            for (int r = 0; r < 8; ++r) {
                float4 a = *(const float4*)&sA[(ty * 8 + r) * F + k];
                acc[r][0] += a.x * b0.x + a.y * b1.x + a.z * b2.x + a.w * b3.x;
                acc[r][1] += a.x * b0.y + a.y * b1.y + a.z * b2.y + a.w * b3.y;
                acc[r][2] += a.x * b0.z + a.y * b1.z + a.z * b2.z + a.w * b3.z;
                acc[r][3] += a.x * b0.w + a.y * b1.w + a.z * b2.w + a.w * b3.w;
            }
        }

        // ---- acc += H @ Wn ----
        #pragma unroll 2
        for (int k = 0; k < F; k += 4) {
            float4 b0 = *(const float4*)&sWn[(k + 0) * F + tx * 4];
            float4 b1 = *(const float4*)&sWn[(k + 1) * F + tx * 4];
            float4 b2 = *(const float4*)&sWn[(k + 2) * F + tx * 4];
            float4 b3 = *(const float4*)&sWn[(k + 3) * F + tx * 4];
            #pragma unroll
            for (int r = 0; r < 8; ++r) {
                float4 a = *(const float4*)&sH[(ty * 8 + r) * F + k];
                acc[r][0] += a.x * b0.x + a.y * b1.x + a.z * b2.x + a.w * b3.x;
                acc[r][1] += a.x * b0.y + a.y * b1.y + a.z * b2.y + a.w * b3.y;
                acc[r][2] += a.x * b0.z + a.y * b1.z + a.z * b2.z + a.w * b3.z;
                acc[r][3] += a.x * b0.w + a.y * b1.w + a.z * b2.w + a.w * b3.w;
            }
        }

        // Epilogue: bias + relu, coalesced float4 store
        #pragma unroll
        for (int r = 0; r < 8; ++r) {
            int node = row0 + ty * 8 + r;
            if (node < N_NODES) {
                float4 o;
                o.x = fmaxf(acc[r][0] + bv.x, 0.f);
                o.y = fmaxf(acc[r][1] + bv.y, 0.f);
                o.z = fmaxf(acc[r][2] + bv.z, 0.f);
                o.w = fmaxf(acc[r][3] + bv.w, 0.f);
                ((float4*)out)[(size_t)node * F4 + tx] = o;
            }
        }
    }
}

// ---------------------------------------------------------------------------
// Launch
// ---------------------------------------------------------------------------
extern "C" void kernel_launch(void* const* d_in, const int* in_sizes, int n_in,
                              void* d_out, int out_size) {
    const float* x   = (const float*)d_in[0];
    const float* Ws  = (const float*)d_in[1];
    const float* Wn  = (const float*)d_in[2];
    const float* b   = (const float*)d_in[3];
    const int*   src = (const int*)d_in[4];
    const int*   dst = (const int*)d_in[5];
    float* out = (float*)d_out;

    cudaFuncSetAttribute(gemm_kernel,
                         cudaFuncAttributeMaxDynamicSharedMemorySize, SMEM_BYTES);

    // 1) zero scratch: 1.6M float4 + deg
    {
        int threads = 256;
        int blocks = (N_NODES * F / 4 + threads - 1) / threads;  // 6250
        zero_kernel<<<blocks, threads>>>();
    }
    // 2) edge scatter: one warp per edge
    {
        int threads = 256;                         // 8 warps/block
        int blocks = (N_EDGES + 7) / 8;            // 75000
        edge_kernel<<<blocks, threads>>>((const float4*)x, src, dst);
    }
    // 3) fused GEMM + mean + bias + relu
    {
        gemm_kernel<<<152, 256, SMEM_BYTES>>>(x, Ws, Wn, b, out);
    }
}

// round 2
// speedup vs baseline: 1.0414x; 1.0414x over previous
#include <cuda_runtime.h>

#define N_NODES 50000
#define N_EDGES 600000
#define F 128           // F_IN == F_OUT == 128
#define F4 (F / 4)      // 32 float4 per row

// Scratch (static device globals — no allocation)
__device__ int g_deg[N_NODES];
__device__ int g_off[N_NODES + 1];
__device__ int g_cursor[N_NODES];
__device__ int g_srcs[N_EDGES];      // edge srcs bucketed by dst (CSR)

// ---------------------------------------------------------------------------
// Kernel 1: zero degree histogram
// ---------------------------------------------------------------------------
__global__ void zero_deg_kernel() {
    int i = blockIdx.x * blockDim.x + threadIdx.x;
    if (i < N_NODES) g_deg[i] = 0;
}

// ---------------------------------------------------------------------------
// Kernel 2: degree histogram (int atomics, avg contention ~12 -> cheap)
// ---------------------------------------------------------------------------
__global__ void deg_kernel(const int* __restrict__ dst) {
    int i = blockIdx.x * blockDim.x + threadIdx.x;
    if (i < N_EDGES) atomicAdd(&g_deg[dst[i]], 1);
}

// ---------------------------------------------------------------------------
// Kernel 3: single-CTA exclusive prefix scan -> offsets + cursor init
// ---------------------------------------------------------------------------
#define SCAN_T 1024
#define SCAN_ITEMS ((N_NODES + SCAN_T - 1) / SCAN_T)   // 49

__global__ void __launch_bounds__(SCAN_T, 1) scan_kernel() {
    __shared__ int ssum[SCAN_T];
    const int tid = threadIdx.x;
    const int base = tid * SCAN_ITEMS;

    int local = 0;
    #pragma unroll 4
    for (int i = 0; i < SCAN_ITEMS; ++i) {
        int idx = base + i;
        if (idx < N_NODES) local += g_deg[idx];
    }
    ssum[tid] = local;
    __syncthreads();
    // Hillis-Steele inclusive scan over 1024 partials
    #pragma unroll
    for (int ofs = 1; ofs < SCAN_T; ofs <<= 1) {
        int v = (tid >= ofs) ? ssum[tid - ofs] : 0;
        __syncthreads();
        ssum[tid] += v;
        __syncthreads();
    }
    int run = ssum[tid] - local;   // exclusive prefix for this thread's chunk
    #pragma unroll 4
    for (int i = 0; i < SCAN_ITEMS; ++i) {
        int idx = base + i;
        if (idx < N_NODES) {
            g_off[idx] = run;
            g_cursor[idx] = run;
            run += g_deg[idx];
        }
    }
    if (tid == SCAN_T - 1) g_off[N_NODES] = run;   // == N_EDGES
}

// ---------------------------------------------------------------------------
// Kernel 4: scatter edge srcs into CSR buckets
// ---------------------------------------------------------------------------
__global__ void scatter_kernel(const int* __restrict__ src,
                               const int* __restrict__ dst) {
    int i = blockIdx.x * blockDim.x + threadIdx.x;
    if (i < N_EDGES) {
        int p = atomicAdd(&g_cursor[dst[i]], 1);
        g_srcs[p] = src[i];
    }
}

// ---------------------------------------------------------------------------
// Kernel 5: fused aggregate + GEMM
//   out = relu(x @ Ws + mean_neigh(x) @ Wn + b)
// Persistent CTAs. Both weights cached fully in SMEM.
// Tile: M=64 rows, N=128 cols. 256 threads, 8x4 micro-tile per thread.
// Each warp aggregates its 8 nodes' neighbor rows on the fly into sH.
// ---------------------------------------------------------------------------
#define TILE_M 64
// SMEM layout (floats): Ws[16384] Wn[16384] A[8192] H[8192]
#define SM_WS   0
#define SM_WN   16384
#define SM_A    32768
#define SM_H    40960
#define SMEM_FLOATS 49152
#define SMEM_BYTES (SMEM_FLOATS * 4)

__global__ void __launch_bounds__(256, 1)
gemm_kernel(const float* __restrict__ x,
            const float* __restrict__ Ws,
            const float* __restrict__ Wn,
            const float* __restrict__ bias,
            float* __restrict__ out) {
    extern __shared__ float sm[];
    float* sWs = sm + SM_WS;
    float* sWn = sm + SM_WN;
    float* sA  = sm + SM_A;
    float* sH  = sm + SM_H;

    const int tid  = threadIdx.x;
    const int lane = tid & 31;   // also column group: cols [4*lane, 4*lane+4)
    const int ty   = tid >> 5;   // warp id; row group: rows [8*ty, 8*ty+8)
    const float4* __restrict__ x4 = (const float4*)x;

    // Load both weight matrices to SMEM once per CTA (coalesced float4).
    for (int i = tid; i < 16384 / 4; i += 256) {
        ((float4*)sWs)[i] = ((const float4*)Ws)[i];
        ((float4*)sWn)[i] = ((const float4*)Wn)[i];
    }
    const float4 bv = ((const float4*)bias)[lane];

    const int numTiles = (N_NODES + TILE_M - 1) / TILE_M;  // 782

    for (int tile = blockIdx.x; tile < numTiles; tile += gridDim.x) {
        const int row0 = tile * TILE_M;

        __syncthreads();   // previous tile's compute done before overwriting smem

        // ---- Load A tile (x rows), coalesced ----
        #pragma unroll
        for (int j = 0; j < 8; ++j) {
            int i = j * 256 + tid;        // float4 index within 64x32 tile
            int r = i >> 5, c = i & 31;
            int node = row0 + r;
            ((float4*)sA)[i] = (node < N_NODES)
                ? x4[(size_t)node * F4 + c]
                : make_float4(0.f, 0.f, 0.f, 0.f);
        }

        // ---- Aggregate neighbors on the fly into sH ----
        // Warp ty handles local rows [8*ty, 8*ty+8). Each lane owns one float4
        // column slice of the 128-float row. 4-way edge unroll for MLP.
        #pragma unroll
        for (int j = 0; j < 8; ++j) {
            int lr = ty * 8 + j;
            int node = row0 + lr;
            float4 a0 = make_float4(0.f, 0.f, 0.f, 0.f);
            float4 a1 = a0, a2 = a0, a3 = a0;
            int beg = 0, end = 0;
            if (node < N_NODES) {
                beg = __ldg(&g_off[node]);
                end = __ldg(&g_off[node + 1]);
            }
            int e = beg;
            for (; e + 4 <= end; e += 4) {
                int s0 = __ldg(&g_srcs[e + 0]);
                int s1 = __ldg(&g_srcs[e + 1]);
                int s2 = __ldg(&g_srcs[e + 2]);
                int s3 = __ldg(&g_srcs[e + 3]);
                float4 v0 = x4[(size_t)s0 * F4 + lane];
                float4 v1 = x4[(size_t)s1 * F4 + lane];
                float4 v2 = x4[(size_t)s2 * F4 + lane];
                float4 v3 = x4[(size_t)s3 * F4 + lane];
                a0.x += v0.x; a0.y += v0.y; a0.z += v0.z; a0.w += v0.w;
                a1.x += v1.x; a1.y += v1.y; a1.z += v1.z; a1.w += v1.w;
                a2.x += v2.x; a2.y += v2.y; a2.z += v2.z; a2.w += v2.w;
                a3.x += v3.x; a3.y += v3.y; a3.z += v3.z; a3.w += v3.w;
            }
            for (; e < end; ++e) {
                int s = __ldg(&g_srcs[e]);
                float4 v = x4[(size_t)s * F4 + lane];
                a0.x += v.x; a0.y += v.y; a0.z += v.z; a0.w += v.w;
            }
            float inv = 1.0f / (float)max(end - beg, 1);
            float4 acc;
            acc.x = (a0.x + a1.x + a2.x + a3.x) * inv;
            acc.y = (a0.y + a1.y + a2.y + a3.y) * inv;
            acc.z = (a0.z + a1.z + a2.z + a3.z) * inv;
            acc.w = (a0.w + a1.w + a2.w + a3.w) * inv;
            *(float4*)&sH[lr * F + lane * 4] = acc;
        }
        __syncthreads();

        float acc[8][4];
        #pragma unroll
        for (int r = 0; r < 8; ++r)
            #pragma unroll
            for (int c = 0; c < 4; ++c) acc[r][c] = 0.f;

        // ---- acc += A @ Ws ----
        #pragma unroll 2
        for (int k = 0; k < F; k += 4) {
            float4 b0 = *(const float4*)&sWs[(k + 0) * F + lane * 4];
            float4 b1 = *(const float4*)&sWs[(k + 1) * F + lane * 4];
            float4 b2 = *(const float4*)&sWs[(k + 2) * F + lane * 4];
            float4 b3 = *(const float4*)&sWs[(k + 3) * F + lane * 4];
            #pragma unroll
            for (int r = 0; r < 8; ++r) {
                float4 a = *(const float4*)&sA[(ty * 8 + r) * F + k];
                acc[r][0] += a.x * b0.x + a.y * b1.x + a.z * b2.x + a.w * b3.x;
                acc[r][1] += a.x * b0.y + a.y * b1.y + a.z * b2.y + a.w * b3.y;
                acc[r][2] += a.x * b0.z + a.y * b1.z + a.z * b2.z + a.w * b3.z;
                acc[r][3] += a.x * b0.w + a.y * b1.w + a.z * b2.w + a.w * b3.w;
            }
        }

        // ---- acc += H @ Wn ----
        #pragma unroll 2
        for (int k = 0; k < F; k += 4) {
            float4 b0 = *(const float4*)&sWn[(k + 0) * F + lane * 4];
            float4 b1 = *(const float4*)&sWn[(k + 1) * F + lane * 4];
            float4 b2 = *(const float4*)&sWn[(k + 2) * F + lane * 4];
            float4 b3 = *(const float4*)&sWn[(k + 3) * F + lane * 4];
            #pragma unroll
            for (int r = 0; r < 8; ++r) {
                float4 a = *(const float4*)&sH[(ty * 8 + r) * F + k];
                acc[r][0] += a.x * b0.x + a.y * b1.x + a.z * b2.x + a.w * b3.x;
                acc[r][1] += a.x * b0.y + a.y * b1.y + a.z * b2.y + a.w * b3.y;
                acc[r][2] += a.x * b0.z + a.y * b1.z + a.z * b2.z + a.w * b3.z;
                acc[r][3] += a.x * b0.w + a.y * b1.w + a.z * b2.w + a.w * b3.w;
            }
        }

        // ---- Epilogue: bias + relu, coalesced float4 store ----
        #pragma unroll
        for (int r = 0; r < 8; ++r) {
            int node = row0 + ty * 8 + r;
            if (node < N_NODES) {
                float4 o;
                o.x = fmaxf(acc[r][0] + bv.x, 0.f);
                o.y = fmaxf(acc[r][1] + bv.y, 0.f);
                o.z = fmaxf(acc[r][2] + bv.z, 0.f);
                o.w = fmaxf(acc[r][3] + bv.w, 0.f);
                ((float4*)out)[(size_t)node * F4 + lane] = o;
            }
        }
    }
}

// ---------------------------------------------------------------------------
// Launch
// ---------------------------------------------------------------------------
extern "C" void kernel_launch(void* const* d_in, const int* in_sizes, int n_in,
                              void* d_out, int out_size) {
    const float* x   = (const float*)d_in[0];
    const float* Ws  = (const float*)d_in[1];
    const float* Wn  = (const float*)d_in[2];
    const float* b   = (const float*)d_in[3];
    const int*   src = (const int*)d_in[4];
    const int*   dst = (const int*)d_in[5];
    float* out = (float*)d_out;

    cudaFuncSetAttribute(gemm_kernel,
                         cudaFuncAttributeMaxDynamicSharedMemorySize, SMEM_BYTES);

    zero_deg_kernel<<<(N_NODES + 255) / 256, 256>>>();
    deg_kernel<<<(N_EDGES + 255) / 256, 256>>>(dst);
    scan_kernel<<<1, SCAN_T>>>();
    scatter_kernel<<<(N_EDGES + 255) / 256, 256>>>(src, dst);
    gemm_kernel<<<152, 256, SMEM_BYTES>>>(x, Ws, Wn, b, out);
}

// round 3
// speedup vs baseline: 1.2472x; 1.1976x over previous
#include <cuda_runtime.h>
#include <cstdint>

#define N_NODES 50000
#define N_EDGES 600000
#define F 128           // F_IN == F_OUT == 128
#define F4 32           // float4 per row
#define TILE_M 64
#define NTILES ((N_NODES + TILE_M - 1) / TILE_M)   // 782
#define GEMM_GRID 148

// Scratch (static device globals — no allocation)
__device__ int g_deg[N_NODES];
__device__ int g_off[N_NODES + 1];
__device__ int g_cursor[N_NODES];
__device__ int g_srcs[N_EDGES];               // edge srcs bucketed by dst (CSR)
__device__ float g_h[(size_t)N_NODES * F];    // mean-aggregated neighbor feats

// ---------------------------------------------------------------------------
// Kernel 1: zero degree histogram
// ---------------------------------------------------------------------------
__global__ void zero_deg_kernel() {
    int i = blockIdx.x * blockDim.x + threadIdx.x;
    if (i < N_NODES) g_deg[i] = 0;
}

// ---------------------------------------------------------------------------
// Kernel 2: degree histogram
// ---------------------------------------------------------------------------
__global__ void deg_kernel(const int* __restrict__ dst) {
    int i = blockIdx.x * blockDim.x + threadIdx.x;
    if (i < N_EDGES) atomicAdd(&g_deg[dst[i]], 1);
}

// ---------------------------------------------------------------------------
// Kernel 3: single-CTA exclusive prefix scan -> offsets + cursor init
// ---------------------------------------------------------------------------
#define SCAN_T 1024
#define SCAN_ITEMS ((N_NODES + SCAN_T - 1) / SCAN_T)   // 49

__global__ void __launch_bounds__(SCAN_T, 1) scan_kernel() {
    __shared__ int ssum[SCAN_T];
    const int tid = threadIdx.x;
    const int base = tid * SCAN_ITEMS;

    int local = 0;
    #pragma unroll 4
    for (int i = 0; i < SCAN_ITEMS; ++i) {
        int idx = base + i;
        if (idx < N_NODES) local += g_deg[idx];
    }
    ssum[tid] = local;
    __syncthreads();
    #pragma unroll
    for (int ofs = 1; ofs < SCAN_T; ofs <<= 1) {
        int v = (tid >= ofs) ? ssum[tid - ofs] : 0;
        __syncthreads();
        ssum[tid] += v;
        __syncthreads();
    }
    int run = ssum[tid] - local;
    #pragma unroll 4
    for (int i = 0; i < SCAN_ITEMS; ++i) {
        int idx = base + i;
        if (idx < N_NODES) {
            g_off[idx] = run;
            g_cursor[idx] = run;
            run += g_deg[idx];
        }
    }
    if (tid == SCAN_T - 1) g_off[N_NODES] = run;
}

// ---------------------------------------------------------------------------
// Kernel 4: scatter edge srcs into CSR buckets
// ---------------------------------------------------------------------------
__global__ void scatter_kernel(const int* __restrict__ src,
                               const int* __restrict__ dst) {
    int i = blockIdx.x * blockDim.x + threadIdx.x;
    if (i < N_EDGES) {
        int p = atomicAdd(&g_cursor[dst[i]], 1);
        g_srcs[p] = src[i];
    }
}

// ---------------------------------------------------------------------------
// Kernel 5: mean aggregation. One warp per node, lane = float4 column slice.
// Pure L2-bandwidth: ~307 MB gather reads + 25.6 MB writes.
// ---------------------------------------------------------------------------
__global__ void agg_kernel(const float4* __restrict__ x4) {
    int gw   = (blockIdx.x * blockDim.x + threadIdx.x) >> 5;
    int lane = threadIdx.x & 31;
    if (gw >= N_NODES) return;

    int beg = __ldg(&g_off[gw]);
    int end = __ldg(&g_off[gw + 1]);

    float4 a0 = make_float4(0.f, 0.f, 0.f, 0.f);
    float4 a1 = a0, a2 = a0, a3 = a0;
    int e = beg;
    for (; e + 4 <= end; e += 4) {
        int s0 = __ldg(&g_srcs[e + 0]);
        int s1 = __ldg(&g_srcs[e + 1]);
        int s2 = __ldg(&g_srcs[e + 2]);
        int s3 = __ldg(&g_srcs[e + 3]);
        float4 v0 = x4[(size_t)s0 * F4 + lane];
        float4 v1 = x4[(size_t)s1 * F4 + lane];
        float4 v2 = x4[(size_t)s2 * F4 + lane];
        float4 v3 = x4[(size_t)s3 * F4 + lane];
        a0.x += v0.x; a0.y += v0.y; a0.z += v0.z; a0.w += v0.w;
        a1.x += v1.x; a1.y += v1.y; a1.z += v1.z; a1.w += v1.w;
        a2.x += v2.x; a2.y += v2.y; a2.z += v2.z; a2.w += v2.w;
        a3.x += v3.x; a3.y += v3.y; a3.z += v3.z; a3.w += v3.w;
    }
    for (; e < end; ++e) {
        int s = __ldg(&g_srcs[e]);
        float4 v = x4[(size_t)s * F4 + lane];
        a0.x += v.x; a0.y += v.y; a0.z += v.z; a0.w += v.w;
    }
    float inv = 1.0f / (float)max(end - beg, 1);
    float4 r;
    r.x = (a0.x + a1.x + a2.x + a3.x) * inv;
    r.y = (a0.y + a1.y + a2.y + a3.y) * inv;
    r.z = (a0.z + a1.z + a2.z + a3.z) * inv;
    r.w = (a0.w + a1.w + a2.w + a3.w) * inv;
    ((float4*)g_h)[(size_t)gw * F4 + lane] = r;
}

// ---------------------------------------------------------------------------
// Kernel 6: GEMM  out = relu(x @ Ws + h @ Wn + b)
// Persistent CTAs, 256 threads. Warp = column-major: lane tx owns cols
// [4*tx, 4*tx+4), warp ty owns rows [8*ty, 8*ty+8). A loads are full-warp
// broadcasts; B loads are conflict-free 512B rows.
// cp.async double-buffered staging of the 64x128 A/H tiles.
// SMEM: Ws+Wn 128KB, 2x32KB stage buffers = 192KB.
// ---------------------------------------------------------------------------
#define SM_W     0            // 32768 floats (Ws then Wn)
#define SM_BUF   32768        // 2 x 8192 floats
#define SMEM_FLOATS (32768 + 2 * 8192)
#define SMEM_BYTES (SMEM_FLOATS * 4)

__device__ __forceinline__ void cp_async_commit() {
    asm volatile("cp.async.commit_group;");
}
template <int N>
__device__ __forceinline__ void cp_async_wait() {
    asm volatile("cp.async.wait_group %0;" :: "n"(N));
}

// Stage a 64-row x 128-col tile (2048 float4) with 256 threads (8 each).
__device__ __forceinline__ void prefetch_stage(const float4* __restrict__ src,
                                               int row0, float* sbuf) {
    const int tid = threadIdx.x;
    #pragma unroll
    for (int t = 0; t < 8; ++t) {
        int i = tid + t * 256;
        int r = i >> 5, c = i & 31;
        int node = row0 + r;
        const float4* g = src + (size_t)node * F4 + c;
        uint32_t sa = (uint32_t)__cvta_generic_to_shared(sbuf + r * F + c * 4);
        int sz = (node < N_NODES) ? 16 : 0;
        asm volatile("cp.async.cg.shared.global [%0], [%1], 16, %2;"
                     :: "r"(sa), "l"(g), "r"(sz));
    }
}

__global__ void __launch_bounds__(256, 1)
gemm_kernel(const float4* __restrict__ x4,
            const float* __restrict__ Ws,
            const float* __restrict__ Wn,
            const float* __restrict__ bias,
            float* __restrict__ out) {
    extern __shared__ float sm[];
    float* sW = sm + SM_W;

    const int tid = threadIdx.x;
    const int tx  = tid & 31;   // col group: cols [4*tx, 4*tx+4)
    const int ty  = tid >> 5;   // warp id == row group: rows [8*ty, 8*ty+8)
    const float4* __restrict__ h4 = (const float4*)g_h;

    // Load both weight matrices into SMEM (coalesced float4).
    for (int i = tid; i < 32768 / 4; i += 256) {
        ((float4*)sW)[i] = (i < 4096) ? ((const float4*)Ws)[i]
                                      : ((const float4*)Wn)[i - 4096];
    }
    const float4 bv = ((const float4*)bias)[tx];

    int tile = blockIdx.x;
    int buf = 0;
    if (tile < NTILES) {
        prefetch_stage(x4, tile * TILE_M, sm + SM_BUF);   // (tile0, stage A)
    }
    cp_async_commit();

    for (; tile < NTILES; tile += GEMM_GRID) {
        const int row0 = tile * TILE_M;

        float acc[8][4];
        #pragma unroll
        for (int r = 0; r < 8; ++r)
            #pragma unroll
            for (int c = 0; c < 4; ++c) acc[r][c] = 0.f;

        #pragma unroll
        for (int s = 0; s < 2; ++s) {
            // Issue prefetch for the next stage into the other buffer.
            int nt = (s == 0) ? tile : tile + GEMM_GRID;
            int ns = (s == 0) ? 1 : 0;
            if (nt < NTILES) {
                prefetch_stage(ns == 0 ? x4 : h4, nt * TILE_M,
                               sm + SM_BUF + (buf ^ 1) * 8192);
            }
            cp_async_commit();
            cp_async_wait<1>();       // current stage's data has landed
            __syncthreads();

            const float* W = sW + s * 16384;
            const float* A = sm + SM_BUF + buf * 8192;

            #pragma unroll 4
            for (int k = 0; k < F; k += 4) {
                float4 b0 = *(const float4*)&W[(k + 0) * F + tx * 4];
                float4 b1 = *(const float4*)&W[(k + 1) * F + tx * 4];
                float4 b2 = *(const float4*)&W[(k + 2) * F + tx * 4];
                float4 b3 = *(const float4*)&W[(k + 3) * F + tx * 4];
                #pragma unroll
                for (int r = 0; r < 8; ++r) {
                    float4 a = *(const float4*)&A[(ty * 8 + r) * F + k];  // warp broadcast
                    acc[r][0] += a.x * b0.x + a.y * b1.x + a.z * b2.x + a.w * b3.x;
                    acc[r][1] += a.x * b0.y + a.y * b1.y + a.z * b2.y + a.w * b3.y;
                    acc[r][2] += a.x * b0.z + a.y * b1.z + a.z * b2.z + a.w * b3.z;
                    acc[r][3] += a.x * b0.w + a.y * b1.w + a.z * b2.w + a.w * b3.w;
                }
            }
            __syncthreads();   // all readers done before next prefetch overwrites
            buf ^= 1;
        }

        // Epilogue: bias + relu, coalesced float4 store (no smem use).
        #pragma unroll
        for (int r = 0; r < 8; ++r) {
            int node = row0 + ty * 8 + r;
            if (node < N_NODES) {
                float4 o;
                o.x = fmaxf(acc[r][0] + bv.x, 0.f);
                o.y = fmaxf(acc[r][1] + bv.y, 0.f);
                o.z = fmaxf(acc[r][2] + bv.z, 0.f);
                o.w = fmaxf(acc[r][3] + bv.w, 0.f);
                ((float4*)out)[(size_t)node * F4 + tx] = o;
            }
        }
    }
}

// ---------------------------------------------------------------------------
// Launch
// ---------------------------------------------------------------------------
extern "C" void kernel_launch(void* const* d_in, const int* in_sizes, int n_in,
                              void* d_out, int out_size) {
    const float* x   = (const float*)d_in[0];
    const float* Ws  = (const float*)d_in[1];
    const float* Wn  = (const float*)d_in[2];
    const float* b   = (const float*)d_in[3];
    const int*   src = (const int*)d_in[4];
    const int*   dst = (const int*)d_in[5];
    float* out = (float*)d_out;

    cudaFuncSetAttribute(gemm_kernel,
                         cudaFuncAttributeMaxDynamicSharedMemorySize, SMEM_BYTES);

    zero_deg_kernel<<<(N_NODES + 255) / 256, 256>>>();
    deg_kernel<<<(N_EDGES + 255) / 256, 256>>>(dst);
    scan_kernel<<<1, SCAN_T>>>();
    scatter_kernel<<<(N_EDGES + 255) / 256, 256>>>(src, dst);
    agg_kernel<<<(N_NODES * 32 + 255) / 256, 256>>>((const float4*)x);
    gemm_kernel<<<GEMM_GRID, 256, SMEM_BYTES>>>((const float4*)x, Ws, Wn, b, out);
}

// round 6
// speedup vs baseline: 1.6086x; 1.2897x over previous
#include <cuda_runtime.h>
#include <cstdint>

#define N_NODES 50000
#define N_EDGES 600000
#define F 128
#define F4 32
#define TILE 128
#define NT ((N_NODES + TILE - 1) / TILE)   // 391
#define GRID 148

// ---------------- scratch (static device globals) ----------------
__device__ int g_deg[N_NODES];
__device__ int g_off[N_NODES + 1];
__device__ int g_cursor[N_NODES];
__device__ int g_srcs[N_EDGES];
__device__ __align__(16) float g_h[(size_t)N_NODES * F];    // tf32-rounded mean-agg
__device__ __align__(16) float g_xr[(size_t)N_NODES * F];   // tf32-rounded x
__device__ __align__(16) float g_B[256 * 128];              // [k][n] rounded [Ws;Wn]

// ---------------- helpers ----------------
__device__ __forceinline__ float rna_tf32(float v) {
    float r; asm("cvt.rna.tf32.f32 %0, %1;" : "=f"(r) : "f"(v)); return r;
}
__device__ __forceinline__ uint32_t smem_u32(const void* p) {
    uint32_t a;
    asm("{ .reg .u64 t; cvta.to.shared.u64 t, %1; cvt.u32.u64 %0, t; }" : "=r"(a) : "l"(p));
    return a;
}
#define CP_COMMIT() asm volatile("cp.async.commit_group;")
#define CP_WAIT2()  asm volatile("cp.async.wait_group 2;")

__device__ __forceinline__ void mma_tf32(float* c, uint32_t a0, uint32_t a1,
                                         uint32_t a2, uint32_t a3,
                                         uint32_t b0, uint32_t b1) {
    asm volatile(
        "mma.sync.aligned.m16n8k8.row.col.f32.tf32.tf32.f32 "
        "{%0,%1,%2,%3}, {%4,%5,%6,%7}, {%8,%9}, {%0,%1,%2,%3};"
        : "+f"(c[0]), "+f"(c[1]), "+f"(c[2]), "+f"(c[3])
        : "r"(a0), "r"(a1), "r"(a2), "r"(a3), "r"(b0), "r"(b1));
}

// ---------------- Kernel 1: zero degree ----------------
__global__ void zero_deg_kernel() {
    int i = blockIdx.x * blockDim.x + threadIdx.x;
    if (i < N_NODES) g_deg[i] = 0;
}
// ---------------- Kernel 2: degree histogram ----------------
__global__ void deg_kernel(const int* __restrict__ dst) {
    int i = blockIdx.x * blockDim.x + threadIdx.x;
    if (i < N_EDGES) atomicAdd(&g_deg[dst[i]], 1);
}
// ---------------- Kernel 3: prefix scan ----------------
#define SCAN_T 1024
#define SCAN_ITEMS ((N_NODES + SCAN_T - 1) / SCAN_T)
__global__ void __launch_bounds__(SCAN_T, 1) scan_kernel() {
    __shared__ int ssum[SCAN_T];
    const int tid = threadIdx.x;
    const int base = tid * SCAN_ITEMS;
    int local = 0;
    #pragma unroll 4
    for (int i = 0; i < SCAN_ITEMS; ++i) {
        int idx = base + i;
        if (idx < N_NODES) local += g_deg[idx];
    }
    ssum[tid] = local;
    __syncthreads();
    #pragma unroll
    for (int ofs = 1; ofs < SCAN_T; ofs <<= 1) {
        int v = (tid >= ofs) ? ssum[tid - ofs] : 0;
        __syncthreads();
        ssum[tid] += v;
        __syncthreads();
    }
    int run = ssum[tid] - local;
    #pragma unroll 4
    for (int i = 0; i < SCAN_ITEMS; ++i) {
        int idx = base + i;
        if (idx < N_NODES) {
            g_off[idx] = run;
            g_cursor[idx] = run;
            run += g_deg[idx];
        }
    }
    if (tid == SCAN_T - 1) g_off[N_NODES] = run;
}
// ---------------- Kernel 4: CSR scatter ----------------
__global__ void scatter_kernel(const int* __restrict__ src,
                               const int* __restrict__ dst) {
    int i = blockIdx.x * blockDim.x + threadIdx.x;
    if (i < N_EDGES) {
        int p = atomicAdd(&g_cursor[dst[i]], 1);
        g_srcs[p] = src[i];
    }
}
// ---------------- Kernel 5: round x -> g_xr ----------------
__global__ void round_x_kernel(const float4* __restrict__ x4) {
    int i = blockIdx.x * blockDim.x + threadIdx.x;
    if (i < N_NODES * F4) {
        float4 v = x4[i];
        v.x = rna_tf32(v.x); v.y = rna_tf32(v.y);
        v.z = rna_tf32(v.z); v.w = rna_tf32(v.w);
        ((float4*)g_xr)[i] = v;
    }
}
// ---------------- Kernel 6: round weights -> g_B[k][n] (no transpose) ----------------
__global__ void wB_kernel(const float* __restrict__ Ws, const float* __restrict__ Wn) {
    int i = blockIdx.x * blockDim.x + threadIdx.x;
    if (i < 256 * 128) {
        float v = (i < 128 * 128) ? Ws[i] : Wn[i - 128 * 128];
        g_B[i] = rna_tf32(v);
    }
}
// ---------------- Kernel 7: mean aggregation (warp per node) ----------------
__global__ void agg_kernel(const float4* __restrict__ x4) {
    int gw   = (blockIdx.x * blockDim.x + threadIdx.x) >> 5;
    int lane = threadIdx.x & 31;
    if (gw >= N_NODES) return;
    int beg = __ldg(&g_off[gw]);
    int end = __ldg(&g_off[gw + 1]);
    float4 a0 = make_float4(0.f, 0.f, 0.f, 0.f);
    float4 a1 = a0, a2 = a0, a3 = a0;
    int e = beg;
    for (; e + 4 <= end; e += 4) {
        int s0 = __ldg(&g_srcs[e + 0]);
        int s1 = __ldg(&g_srcs[e + 1]);
        int s2 = __ldg(&g_srcs[e + 2]);
        int s3 = __ldg(&g_srcs[e + 3]);
        float4 v0 = x4[(size_t)s0 * F4 + lane];
        float4 v1 = x4[(size_t)s1 * F4 + lane];
        float4 v2 = x4[(size_t)s2 * F4 + lane];
        float4 v3 = x4[(size_t)s3 * F4 + lane];
        a0.x += v0.x; a0.y += v0.y; a0.z += v0.z; a0.w += v0.w;
        a1.x += v1.x; a1.y += v1.y; a1.z += v1.z; a1.w += v1.w;
        a2.x += v2.x; a2.y += v2.y; a2.z += v2.z; a2.w += v2.w;
        a3.x += v3.x; a3.y += v3.y; a3.z += v3.z; a3.w += v3.w;
    }
    for (; e < end; ++e) {
        int s = __ldg(&g_srcs[e]);
        float4 v = x4[(size_t)s * F4 + lane];
        a0.x += v.x; a0.y += v.y; a0.z += v.z; a0.w += v.w;
    }
    float inv = 1.0f / (float)max(end - beg, 1);
    float4 r;
    r.x = rna_tf32((a0.x + a1.x + a2.x + a3.x) * inv);
    r.y = rna_tf32((a0.y + a1.y + a2.y + a3.y) * inv);
    r.z = rna_tf32((a0.z + a1.z + a2.z + a3.z) * inv);
    r.w = rna_tf32((a0.w + a1.w + a2.w + a3.w) * inv);
    ((float4*)g_h)[(size_t)gw * F4 + lane] = r;
}

// ---------------- Kernel 8: tf32 mma.sync GEMM ----------------
// D[50000,128] = [xr | h] @ [Ws; Wn]  (+bias, relu)
// SMEM (floats): B[k=256][n=128 rotated] at B_F, 3x A chunk bufs (128x32 rotated)
// Rotations (conflict-free fragment LDS, cp.async-16B compatible):
//   B: element (k,n) stored at k*128 + ((n + 8k) & 127)
//   A: element (r,c) stored at r*32  + ((c + 4r) & 31)
#define B_F  128                  // after 128-float pad (unused bias slot)
#define A_F  (B_F + 32768)
#define SMEM_FLOATS (A_F + 3 * 4096)
#define SMEM_BYTES  (SMEM_FLOATS * 4)

__device__ __forceinline__ void prefetch_chunk(uint32_t sb, int tid, int bid, int s) {
    int t = bid + (s >> 3) * GRID;
    if (t < NT) {
        int ck = s & 7;
        const float* base = (ck < 4) ? g_xr : g_h;
        int cf = (ck & 3) * 32;                 // float col offset within source row
        uint32_t dbase = sb + (A_F + (s % 3) * 4096) * 4;
        #pragma unroll
        for (int rep = 0; rep < 4; ++rep) {
            int i = tid + rep * 256;            // 0..1023 : (row, 16B-unit)
            int r = i >> 3, u = i & 7;
            int node = t * TILE + r;
            const float* g = base + (size_t)node * F + cf + u * 4;
            uint32_t dst = dbase + r * 128 + (((u + r) & 7) << 4);
            int sz = (node < N_NODES) ? 16 : 0;
            asm volatile("cp.async.cg.shared.global [%0], [%1], 16, %2;"
                         :: "r"(dst), "l"(g), "r"(sz));
        }
    }
    CP_COMMIT();
}

__global__ void __launch_bounds__(256, 1)
gemm_kernel(const float* __restrict__ bias, float* __restrict__ out) {
    extern __shared__ float sm[];
    uint32_t sb = smem_u32(sm);
    const int tid = threadIdx.x;
    const int wid = tid >> 5, lane = tid & 31;
    const int gid = lane >> 2, tig = lane & 3;
    const int bid = blockIdx.x;
    const int m_base = (wid >> 2) * 64;        // warp rows [m_base, m_base+64)
    const int n_base = (wid & 3) * 32;         // warp cols [n_base, n_base+32)

    // Per-thread bias (cols n_base + nt*8 + 2*tig, +1)
    float2 bv[4];
    #pragma unroll
    for (int nt = 0; nt < 4; ++nt) {
        int n = n_base + nt * 8 + 2 * tig;
        bv[nt] = make_float2(__ldg(&bias[n]), __ldg(&bias[n + 1]));
    }

    // Load B (256x128) into rotated SMEM layout. 8192 16B-units.
    for (int i = tid; i < 8192; i += 256) {
        int k = i >> 5, u = i & 31;
        uint32_t dst = sb + B_F * 4 + k * 512 + (((u + 2 * k) & 31) << 4);
        asm volatile("cp.async.cg.shared.global [%0], [%1], 16;"
                     :: "r"(dst), "l"(g_B + k * 128 + u * 4));
    }
    CP_COMMIT();
    prefetch_chunk(sb, tid, bid, 0);
    prefetch_chunk(sb, tid, bid, 1);
    prefetch_chunk(sb, tid, bid, 2);

    const uint32_t* Bs = (const uint32_t*)(sm + B_F);
    const int ntile_cta = (NT - 1 - bid) / GRID + 1;
    const int nstream = ntile_cta * 8;

    float acc[4][4][4];
    #pragma unroll
    for (int mt = 0; mt < 4; ++mt)
        #pragma unroll
        for (int nt = 0; nt < 4; ++nt)
            #pragma unroll
            for (int q = 0; q < 4; ++q) acc[mt][nt][q] = 0.f;

    for (int s = 0; s < nstream; ++s) {
        CP_WAIT2();                 // chunk s (and B on first iter) landed
        __syncthreads();

        const uint32_t* As = (const uint32_t*)(sm + A_F + (s % 3) * 4096);
        const int kg0 = (s & 7) * 32;     // global k base of this chunk

        #pragma unroll
        for (int ks = 0; ks < 4; ++ks) {
            const int k0 = ks * 8;
            // B fragments (conflict-free: banks = gid + 8*tig)
            uint32_t bf[4][2];
            #pragma unroll
            for (int nt = 0; nt < 4; ++nt) {
                int n  = n_base + nt * 8 + gid;
                int ka = kg0 + k0 + tig;
                int kb = ka + 4;
                bf[nt][0] = Bs[ka * 128 + ((n + 8 * ka) & 127)];
                bf[nt][1] = Bs[kb * 128 + ((n + 8 * kb) & 127)];
            }
            // A fragments (conflict-free: banks = tig + 4*gid) + MMAs
            #pragma unroll
            for (int mt = 0; mt < 4; ++mt) {
                int r0 = m_base + mt * 16 + gid;
                int r1 = r0 + 8;
                int c0 = k0 + tig, c1 = c0 + 4;
                uint32_t a0 = As[r0 * 32 + ((c0 + 4 * r0) & 31)];
                uint32_t a1 = As[r1 * 32 + ((c0 + 4 * r1) & 31)];
                uint32_t a2 = As[r0 * 32 + ((c1 + 4 * r0) & 31)];
                uint32_t a3 = As[r1 * 32 + ((c1 + 4 * r1) & 31)];
                #pragma unroll
                for (int nt = 0; nt < 4; ++nt)
                    mma_tf32(acc[mt][nt], a0, a1, a2, a3, bf[nt][0], bf[nt][1]);
            }
        }
        __syncthreads();            // readers done before buffer reuse
        prefetch_chunk(sb, tid, bid, s + 3);

        if ((s & 7) == 7) {
            // ---- epilogue: bias + relu + store, then reset acc ----
            const int tile = bid + (s >> 3) * GRID;
            const int rowb = tile * TILE;
            #pragma unroll
            for (int mt = 0; mt < 4; ++mt) {
                int r0 = rowb + m_base + mt * 16 + gid;
                int r1 = r0 + 8;
                #pragma unroll
                for (int nt = 0; nt < 4; ++nt) {
                    int n = n_base + nt * 8 + 2 * tig;
                    if (r0 < N_NODES) {
                        float2 v;
                        v.x = fmaxf(acc[mt][nt][0] + bv[nt].x, 0.f);
                        v.y = fmaxf(acc[mt][nt][1] + bv[nt].y, 0.f);
                        *(float2*)&out[(size_t)r0 * F + n] = v;
                    }
                    if (r1 < N_NODES) {
                        float2 v;
                        v.x = fmaxf(acc[mt][nt][2] + bv[nt].x, 0.f);
                        v.y = fmaxf(acc[mt][nt][3] + bv[nt].y, 0.f);
                        *(float2*)&out[(size_t)r1 * F + n] = v;
                    }
                    acc[mt][nt][0] = acc[mt][nt][1] = 0.f;
                    acc[mt][nt][2] = acc[mt][nt][3] = 0.f;
                }
            }
        }
    }
}

// ---------------- Launch ----------------
extern "C" void kernel_launch(void* const* d_in, const int* in_sizes, int n_in,
                              void* d_out, int out_size) {
    const float* x   = (const float*)d_in[0];
    const float* Ws  = (const float*)d_in[1];
    const float* Wn  = (const float*)d_in[2];
    const float* b   = (const float*)d_in[3];
    const int*   src = (const int*)d_in[4];
    const int*   dst = (const int*)d_in[5];
    float* out = (float*)d_out;

    cudaFuncSetAttribute(gemm_kernel,
                         cudaFuncAttributeMaxDynamicSharedMemorySize, SMEM_BYTES);

    zero_deg_kernel<<<(N_NODES + 255) / 256, 256>>>();
    deg_kernel<<<(N_EDGES + 255) / 256, 256>>>(dst);
    scan_kernel<<<1, SCAN_T>>>();
    scatter_kernel<<<(N_EDGES + 255) / 256, 256>>>(src, dst);
    round_x_kernel<<<(N_NODES * F4 + 255) / 256, 256>>>((const float4*)x);
    wB_kernel<<<(256 * 128 + 255) / 256, 256>>>(Ws, Wn);
    agg_kernel<<<(N_NODES * 32 + 255) / 256, 256>>>((const float4*)x);
    gemm_kernel<<<GRID, 256, SMEM_BYTES>>>(b, out);
}

// round 7
// speedup vs baseline: 2.9452x; 1.8310x over previous
#include <cuda_runtime.h>
#include <cstdint>

#define N_NODES 50000
#define N_EDGES 600000
#define F 128
#define F4 32
#define TILE 128
#define NT ((N_NODES + TILE - 1) / TILE)   // 391
#define GRID 148

// ---------------- scratch (static device globals) ----------------
__device__ int g_deg[N_NODES];
__device__ int g_off[N_NODES];
__device__ int g_cursor[N_NODES];
__device__ int g_total;
__device__ int g_srcs[N_EDGES];
__device__ __align__(16) float g_h[(size_t)N_NODES * F];    // tf32-rounded mean-agg

// ---------------- helpers ----------------
__device__ __forceinline__ float rna_tf32(float v) {
    float r; asm("cvt.rna.tf32.f32 %0, %1;" : "=f"(r) : "f"(v)); return r;
}
__device__ __forceinline__ uint32_t smem_u32(const void* p) {
    uint32_t a;
    asm("{ .reg .u64 t; cvta.to.shared.u64 t, %1; cvt.u32.u64 %0, t; }" : "=r"(a) : "l"(p));
    return a;
}
#define CP_COMMIT() asm volatile("cp.async.commit_group;")
#define CP_WAIT2()  asm volatile("cp.async.wait_group 2;")

__device__ __forceinline__ void mma_tf32(float* c, uint32_t a0, uint32_t a1,
                                         uint32_t a2, uint32_t a3,
                                         uint32_t b0, uint32_t b1) {
    asm volatile(
        "mma.sync.aligned.m16n8k8.row.col.f32.tf32.tf32.f32 "
        "{%0,%1,%2,%3}, {%4,%5,%6,%7}, {%8,%9}, {%0,%1,%2,%3};"
        : "+f"(c[0]), "+f"(c[1]), "+f"(c[2]), "+f"(c[3])
        : "r"(a0), "r"(a1), "r"(a2), "r"(a3), "r"(b0), "r"(b1));
}

// ---------------- Kernel 1: zero degree + total ----------------
__global__ void zero_deg_kernel() {
    int i = blockIdx.x * blockDim.x + threadIdx.x;
    if (i < N_NODES / 4) ((int4*)g_deg)[i] = make_int4(0, 0, 0, 0);
    if (i == 0) {
        g_total = 0;
        // tail (N_NODES not multiple of 4 safe-guard; 50000/4=12500 exact)
    }
}

// ---------------- Kernel 2: degree histogram (4 edges/thread, no-return atomics) ----------------
__global__ void deg_kernel(const int4* __restrict__ dst4) {
    int i = blockIdx.x * blockDim.x + threadIdx.x;
    if (i < N_EDGES / 4) {
        int4 d = dst4[i];
        atomicAdd(&g_deg[d.x], 1);
        atomicAdd(&g_deg[d.y], 1);
        atomicAdd(&g_deg[d.z], 1);
        atomicAdd(&g_deg[d.w], 1);
    }
}

// ---------------- Kernel 3: block-scan offsets (multi-CTA; atomic block base) ----------------
__global__ void __launch_bounds__(256) offsets_kernel() {
    __shared__ int swarp[8];
    __shared__ int sbase;
    const int tid = threadIdx.x;
    const int i = blockIdx.x * 256 + tid;
    const int lane = tid & 31, w = tid >> 5;
    int d = (i < N_NODES) ? g_deg[i] : 0;
    int v = d;
    #pragma unroll
    for (int o = 1; o < 32; o <<= 1) {
        int t = __shfl_up_sync(0xFFFFFFFF, v, o);
        if (lane >= o) v += t;
    }
    if (lane == 31) swarp[w] = v;
    __syncthreads();
    if (tid == 0) {
        int run = 0;
        #pragma unroll
        for (int j = 0; j < 8; ++j) { int t = swarp[j]; swarp[j] = run; run += t; }
        sbase = atomicAdd(&g_total, run);
    }
    __syncthreads();
    if (i < N_NODES) {
        int off = sbase + swarp[w] + v - d;     // exclusive prefix
        g_off[i] = off;
        g_cursor[i] = off;
    }
}

// ---------------- Kernel 4: CSR scatter (4 edges/thread) ----------------
__global__ void scatter_kernel(const int4* __restrict__ src4,
                               const int4* __restrict__ dst4) {
    int i = blockIdx.x * blockDim.x + threadIdx.x;
    if (i < N_EDGES / 4) {
        int4 s = src4[i];
        int4 d = dst4[i];
        int p0 = atomicAdd(&g_cursor[d.x], 1);
        int p1 = atomicAdd(&g_cursor[d.y], 1);
        int p2 = atomicAdd(&g_cursor[d.z], 1);
        int p3 = atomicAdd(&g_cursor[d.w], 1);
        g_srcs[p0] = s.x;
        g_srcs[p1] = s.y;
        g_srcs[p2] = s.z;
        g_srcs[p3] = s.w;
    }
}

// ---------------- Kernel 5: mean aggregation (warp per node), tf32-round output ----------------
__global__ void agg_kernel(const float4* __restrict__ x4) {
    int gw   = (blockIdx.x * blockDim.x + threadIdx.x) >> 5;
    int lane = threadIdx.x & 31;
    if (gw >= N_NODES) return;
    int beg = __ldg(&g_off[gw]);
    int cnt = __ldg(&g_deg[gw]);
    int end = beg + cnt;
    float4 a0 = make_float4(0.f, 0.f, 0.f, 0.f);
    float4 a1 = a0, a2 = a0, a3 = a0;
    int e = beg;
    for (; e + 4 <= end; e += 4) {
        int s0 = __ldg(&g_srcs[e + 0]);
        int s1 = __ldg(&g_srcs[e + 1]);
        int s2 = __ldg(&g_srcs[e + 2]);
        int s3 = __ldg(&g_srcs[e + 3]);
        float4 v0 = x4[(size_t)s0 * F4 + lane];
        float4 v1 = x4[(size_t)s1 * F4 + lane];
        float4 v2 = x4[(size_t)s2 * F4 + lane];
        float4 v3 = x4[(size_t)s3 * F4 + lane];
        a0.x += v0.x; a0.y += v0.y; a0.z += v0.z; a0.w += v0.w;
        a1.x += v1.x; a1.y += v1.y; a1.z += v1.z; a1.w += v1.w;
        a2.x += v2.x; a2.y += v2.y; a2.z += v2.z; a2.w += v2.w;
        a3.x += v3.x; a3.y += v3.y; a3.z += v3.z; a3.w += v3.w;
    }
    for (; e < end; ++e) {
        int s = __ldg(&g_srcs[e]);
        float4 v = x4[(size_t)s * F4 + lane];
        a0.x += v.x; a0.y += v.y; a0.z += v.z; a0.w += v.w;
    }
    float inv = 1.0f / (float)max(cnt, 1);
    float4 r;
    r.x = rna_tf32((a0.x + a1.x + a2.x + a3.x) * inv);
    r.y = rna_tf32((a0.y + a1.y + a2.y + a3.y) * inv);
    r.z = rna_tf32((a0.z + a1.z + a2.z + a3.z) * inv);
    r.w = rna_tf32((a0.w + a1.w + a2.w + a3.w) * inv);
    ((float4*)g_h)[(size_t)gw * F4 + lane] = r;
}

// ---------------- Kernel 6: tf32 mma.sync GEMM ----------------
// D[50000,128] = [x | h] @ [Ws; Wn]  (+bias, relu). x and B rounded IN SMEM.
// SMEM (floats): pad(128), B[k=256][n=128 rotated], 3x A chunk bufs (128x32 rotated)
//   B: element (k,n) at k*128 + ((n + 8k) & 127)
//   A: element (r,c) at r*32  + ((c + 4r) & 31)
#define B_F  128
#define A_F  (B_F + 32768)
#define SMEM_FLOATS (A_F + 3 * 4096)
#define SMEM_BYTES  (SMEM_FLOATS * 4)

__device__ __forceinline__ void prefetch_chunk(uint32_t sb, int tid, int bid, int s,
                                               const float* __restrict__ x) {
    int t = bid + (s >> 3) * GRID;
    if (t < NT) {
        int ck = s & 7;
        const float* base = (ck < 4) ? x : g_h;
        int cf = (ck & 3) * 32;                 // float col offset within source row
        uint32_t dbase = sb + (A_F + (s % 3) * 4096) * 4;
        #pragma unroll
        for (int rep = 0; rep < 4; ++rep) {
            int i = tid + rep * 256;            // 0..1023 : (row, 16B-unit)
            int r = i >> 3, u = i & 7;
            int node = t * TILE + r;
            const float* g = base + (size_t)node * F + cf + u * 4;
            uint32_t dst = dbase + r * 128 + (((u + r) & 7) << 4);
            int sz = (node < N_NODES) ? 16 : 0;
            asm volatile("cp.async.cg.shared.global [%0], [%1], 16, %2;"
                         :: "r"(dst), "l"(g), "r"(sz));
        }
    }
    CP_COMMIT();
}

__global__ void __launch_bounds__(256, 1)
gemm_kernel(const float* __restrict__ x,
            const float* __restrict__ Ws,
            const float* __restrict__ Wn,
            const float* __restrict__ bias,
            float* __restrict__ out) {
    extern __shared__ float sm[];
    uint32_t sb = smem_u32(sm);
    const int tid = threadIdx.x;
    const int wid = tid >> 5, lane = tid & 31;
    const int gid = lane >> 2, tig = lane & 3;
    const int bid = blockIdx.x;
    const int m_base = (wid >> 2) * 64;        // warp rows [m_base, m_base+64)
    const int n_base = (wid & 3) * 32;         // warp cols [n_base, n_base+32)

    float2 bv[4];
    #pragma unroll
    for (int nt = 0; nt < 4; ++nt) {
        int n = n_base + nt * 8 + 2 * tig;
        bv[nt] = make_float2(__ldg(&bias[n]), __ldg(&bias[n + 1]));
    }

    // Load B = [Ws;Wn] (256x128) straight from inputs into rotated layout.
    for (int i = tid; i < 8192; i += 256) {
        int k = i >> 5, u = i & 31;
        const float* src = (k < 128) ? Ws + k * 128 + u * 4
                                     : Wn + (k - 128) * 128 + u * 4;
        uint32_t dst = sb + B_F * 4 + k * 512 + (((u + 2 * k) & 31) << 4);
        asm volatile("cp.async.cg.shared.global [%0], [%1], 16;"
                     :: "r"(dst), "l"(src));
    }
    CP_COMMIT();
    prefetch_chunk(sb, tid, bid, 0, x);
    prefetch_chunk(sb, tid, bid, 1, x);
    prefetch_chunk(sb, tid, bid, 2, x);

    const uint32_t* Bs = (const uint32_t*)(sm + B_F);
    const int ntile_cta = (bid < NT) ? ((NT - 1 - bid) / GRID + 1) : 0;
    const int nstream = ntile_cta * 8;

    float acc[4][4][4];
    #pragma unroll
    for (int mt = 0; mt < 4; ++mt)
        #pragma unroll
        for (int nt = 0; nt < 4; ++nt)
            #pragma unroll
            for (int q = 0; q < 4; ++q) acc[mt][nt][q] = 0.f;

    for (int s = 0; s < nstream; ++s) {
        CP_WAIT2();                 // chunk s (and B on first iter) landed
        __syncthreads();

        // ---- RNA-round landed data in SMEM (idempotent on h chunks) ----
        if (s == 0) {
            float4* Bp = (float4*)(sm + B_F);
            #pragma unroll
            for (int rep = 0; rep < 32; ++rep) {
                float4 v = Bp[tid + rep * 256];
                v.x = rna_tf32(v.x); v.y = rna_tf32(v.y);
                v.z = rna_tf32(v.z); v.w = rna_tf32(v.w);
                Bp[tid + rep * 256] = v;
            }
        }
        {
            float4* Ap = (float4*)(sm + A_F + (s % 3) * 4096);
            #pragma unroll
            for (int rep = 0; rep < 4; ++rep) {
                float4 v = Ap[tid + rep * 256];
                v.x = rna_tf32(v.x); v.y = rna_tf32(v.y);
                v.z = rna_tf32(v.z); v.w = rna_tf32(v.w);
                Ap[tid + rep * 256] = v;
            }
        }
        __syncthreads();

        const uint32_t* As = (const uint32_t*)(sm + A_F + (s % 3) * 4096);
        const int kg0 = (s & 7) * 32;     // global k base of this chunk

        #pragma unroll
        for (int ks = 0; ks < 4; ++ks) {
            const int k0 = ks * 8;
            uint32_t bf[4][2];
            #pragma unroll
            for (int nt = 0; nt < 4; ++nt) {
                int n  = n_base + nt * 8 + gid;
                int ka = kg0 + k0 + tig;
                int kb = ka + 4;
                bf[nt][0] = Bs[ka * 128 + ((n + 8 * ka) & 127)];
                bf[nt][1] = Bs[kb * 128 + ((n + 8 * kb) & 127)];
            }
            #pragma unroll
            for (int mt = 0; mt < 4; ++mt) {
                int r0 = m_base + mt * 16 + gid;
                int r1 = r0 + 8;
                int c0 = k0 + tig, c1 = c0 + 4;
                uint32_t a0 = As[r0 * 32 + ((c0 + 4 * r0) & 31)];
                uint32_t a1 = As[r1 * 32 + ((c0 + 4 * r1) & 31)];
                uint32_t a2 = As[r0 * 32 + ((c1 + 4 * r0) & 31)];
                uint32_t a3 = As[r1 * 32 + ((c1 + 4 * r1) & 31)];
                #pragma unroll
                for (int nt = 0; nt < 4; ++nt)
                    mma_tf32(acc[mt][nt], a0, a1, a2, a3, bf[nt][0], bf[nt][1]);
            }
        }
        __syncthreads();            // readers done before buffer reuse
        prefetch_chunk(sb, tid, bid, s + 3, x);

        if ((s & 7) == 7) {
            // ---- epilogue: bias + relu + store, reset acc ----
            const int tile = bid + (s >> 3) * GRID;
            const int rowb = tile * TILE;
            #pragma unroll
            for (int mt = 0; mt < 4; ++mt) {
                int r0 = rowb + m_base + mt * 16 + gid;
                int r1 = r0 + 8;
                #pragma unroll
                for (int nt = 0; nt < 4; ++nt) {
                    int n = n_base + nt * 8 + 2 * tig;
                    if (r0 < N_NODES) {
                        float2 v;
                        v.x = fmaxf(acc[mt][nt][0] + bv[nt].x, 0.f);
                        v.y = fmaxf(acc[mt][nt][1] + bv[nt].y, 0.f);
                        *(float2*)&out[(size_t)r0 * F + n] = v;
                    }
                    if (r1 < N_NODES) {
                        float2 v;
                        v.x = fmaxf(acc[mt][nt][2] + bv[nt].x, 0.f);
                        v.y = fmaxf(acc[mt][nt][3] + bv[nt].y, 0.f);
                        *(float2*)&out[(size_t)r1 * F + n] = v;
                    }
                    acc[mt][nt][0] = acc[mt][nt][1] = 0.f;
                    acc[mt][nt][2] = acc[mt][nt][3] = 0.f;
                }
            }
        }
    }
}

// ---------------- Launch ----------------
extern "C" void kernel_launch(void* const* d_in, const int* in_sizes, int n_in,
                              void* d_out, int out_size) {
    const float* x   = (const float*)d_in[0];
    const float* Ws  = (const float*)d_in[1];
    const float* Wn  = (const float*)d_in[2];
    const float* b   = (const float*)d_in[3];
    const int*   src = (const int*)d_in[4];
    const int*   dst = (const int*)d_in[5];
    float* out = (float*)d_out;

    cudaFuncSetAttribute(gemm_kernel,
                         cudaFuncAttributeMaxDynamicSharedMemorySize, SMEM_BYTES);

    zero_deg_kernel<<<(N_NODES / 4 + 255) / 256, 256>>>();
    deg_kernel<<<(N_EDGES / 4 + 255) / 256, 256>>>((const int4*)dst);
    offsets_kernel<<<(N_NODES + 255) / 256, 256>>>();
    scatter_kernel<<<(N_EDGES / 4 + 255) / 256, 256>>>((const int4*)src, (const int4*)dst);
    agg_kernel<<<(N_NODES * 32 + 255) / 256, 256>>>((const float4*)x);
    gemm_kernel<<<GRID, 256, SMEM_BYTES>>>(x, Ws, Wn, b, out);
}